// round 8
// baseline (speedup 1.0000x reference)
#include <cuda_runtime.h>
#include <cstdint>

// ---------------------------------------------------------------------------
// Problem constants
// ---------------------------------------------------------------------------
#define NB 128          // batch
#define NA 64           // agents
#define NM 512          // map tokens
#define NH 128          // hidden
#define NHEAD 8
#define HD 16           // head dim
#define NROWS (NB*NA)   // 8192
#define KVROWS (NB*NM)  // 65536

// ---------------------------------------------------------------------------
// Scratch (device globals — allocation-free)
// ---------------------------------------------------------------------------
__device__ float g_kh[KVROWS*NH];      // 32 MB  precomputed K heads
__device__ float g_vh[KVROWS*NH];      // 32 MB  precomputed V heads
__device__ float g_state[NROWS*2];
__device__ float g_h[NROWS*NH];
__device__ float g_c[NROWS*NH];
__device__ float g_e0[NROWS*NH];       // MLP output
__device__ float g_q[NROWS*NH];        // Q projection
__device__ float g_attn[NROWS*NH];     // attention output (pre O-proj)
__device__ float g_x[NROWS*NH];        // O-projected (LSTM input)
__device__ float g_gates[NROWS*4*NH];  // 16 MB
__device__ float g_bcomb[4*NH];        // b_ih + b_hh
__device__ float g_maskadd[NB*NM];     // additive attention mask (0 / -1e30)
__device__ int   g_curav[NROWS];       // current availability (0/1)
__device__ int   g_viol[4];            // dtype-detector violation flags

// ---------------------------------------------------------------------------
// Packed fp32x2 FMA (Blackwell FFMA2) + helpers
// ---------------------------------------------------------------------------
__device__ __forceinline__ float2 ffma2(float2 a, float2 b, float2 c) {
    unsigned long long ua = *reinterpret_cast<unsigned long long*>(&a);
    unsigned long long ub = *reinterpret_cast<unsigned long long*>(&b);
    unsigned long long uc = *reinterpret_cast<unsigned long long*>(&c);
    unsigned long long ud;
    asm("fma.rn.f32x2 %0, %1, %2, %3;" : "=l"(ud) : "l"(ua), "l"(ub), "l"(uc));
    return *reinterpret_cast<float2*>(&ud);
}
__device__ __forceinline__ float2 shfl_xor_f2(float2 v, int m) {
    unsigned long long u = *reinterpret_cast<unsigned long long*>(&v);
    u = __shfl_xor_sync(0xffffffffu, u, m);
    return *reinterpret_cast<float2*>(&u);
}
__device__ __forceinline__ float2 add2(float2 a, float2 b) {
    return make_float2(a.x + b.x, a.y + b.y);
}
__device__ __forceinline__ float sigm(float x) {
    return 1.0f / (1.0f + __expf(-x));
}

// ---------------------------------------------------------------------------
// Bool-dtype detector. We only know the ELEMENT count N of a boolean input,
// not its byte width. Scan the first N/4 32-bit words (always in-bounds for
// every candidate format):
//   int32 bool  -> every word is 0 or 1
//   float32 bool-> every word is 0 or 0x3F800000
//   byte bool   -> words pack 4 flags (e.g. 0x01010101) violating both
// The first map columns / all current availabilities are True, so at least
// one nonzero word is always observed -> classification is unambiguous.
// viol[0]: not-int32 evidence, viol[1]: not-float32 evidence.
// ---------------------------------------------------------------------------
__global__ void detect_kernel(const unsigned int* __restrict__ p, int nwords, int slot)
{
    int i = blockIdx.x*blockDim.x + threadIdx.x;
    if (i >= nwords) return;
    unsigned int w = p[i];
    if (w > 1u)                      atomicOr(&g_viol[slot + 0], 1);
    if (w != 0u && w != 0x3F800000u) atomicOr(&g_viol[slot + 1], 1);
}

__device__ __forceinline__ bool read_bool(const void* p, int idx, int viol32, int violf32)
{
    if (viol32 == 0)  return ((const int*)p)[idx] != 0;
    if (violf32 == 0) return ((const float*)p)[idx] != 0.0f;
    return ((const unsigned char*)p)[idx] != 0;
}

// Build additive attention mask + current-availability flags (once per launch).
__global__ void build_mask_kernel(const void* __restrict__ map_avail,
                                  const void* __restrict__ cur_avail)
{
    int i = blockIdx.x*blockDim.x + threadIdx.x;
    int v32m = g_viol[0], vf32m = g_viol[1];
    int v32c = g_viol[2], vf32c = g_viol[3];
    if (i < NB*NM)
        g_maskadd[i] = read_bool(map_avail, i, v32m, vf32m) ? 0.0f : -1e30f;
    if (i < NROWS)
        g_curav[i] = read_bool(cur_avail, i, v32c, vf32c) ? 1 : 0;
}

// ---------------------------------------------------------------------------
// Generic tiled GEMM:  Y[N,J] = X[N,K] @ W[J,K]^T (+bias) (+=Y if ACCUM)
// Requirements: N % 64 == 0, J % 128 == 0, K % 32 == 0.
// grid = (N/64, J/128), block = 128 threads. FFMA2 microkernel (8x8/thread).
// ---------------------------------------------------------------------------
template<bool ACCUM>
__global__ __launch_bounds__(128)
void gemm_tn(const float* __restrict__ X, const float* __restrict__ W,
             const float* __restrict__ bias, float* __restrict__ Y,
             int K, int J)
{
    __shared__ float Xs[64][33];
    __shared__ float Ws[32][130];

    const int tid = threadIdx.x;
    const int tx = tid & 15;          // col group: cols tx*2 + jj*32
    const int ty = tid >> 4;          // row group: rows ty*8 .. ty*8+7
    const int rowBase = blockIdx.x << 6;
    const int colBase = blockIdx.y << 7;

    float2 acc[8][4];
    #pragma unroll
    for (int i = 0; i < 8; ++i)
        #pragma unroll
        for (int jj = 0; jj < 4; ++jj)
            acc[i][jj] = make_float2(0.0f, 0.0f);

    for (int k0 = 0; k0 < K; k0 += 32) {
        // X tile: 64x32 = 512 float4 slots, 4 per thread
        #pragma unroll
        for (int i = 0; i < 4; ++i) {
            int s = tid + (i << 7);
            int m = s >> 3, kq = (s & 7) << 2;
            float4 v = *reinterpret_cast<const float4*>(&X[(size_t)(rowBase + m)*K + k0 + kq]);
            Xs[m][kq + 0] = v.x; Xs[m][kq + 1] = v.y;
            Xs[m][kq + 2] = v.z; Xs[m][kq + 3] = v.w;
        }
        // W tile (transposed into smem): 128x32 = 1024 float4 slots, 8 per thread
        #pragma unroll
        for (int i = 0; i < 8; ++i) {
            int s = tid + (i << 7);
            int j = s >> 3, kq = (s & 7) << 2;
            float4 v = *reinterpret_cast<const float4*>(&W[(size_t)(colBase + j)*K + k0 + kq]);
            Ws[kq + 0][j] = v.x; Ws[kq + 1][j] = v.y;
            Ws[kq + 2][j] = v.z; Ws[kq + 3][j] = v.w;
        }
        __syncthreads();

        #pragma unroll
        for (int k = 0; k < 32; ++k) {
            float a[8];
            #pragma unroll
            for (int i = 0; i < 8; ++i) a[i] = Xs[(ty << 3) + i][k];
            float2 b[4];
            #pragma unroll
            for (int jj = 0; jj < 4; ++jj)
                b[jj] = *reinterpret_cast<const float2*>(&Ws[k][(tx << 1) + (jj << 5)]);
            #pragma unroll
            for (int i = 0; i < 8; ++i) {
                float2 av = make_float2(a[i], a[i]);
                #pragma unroll
                for (int jj = 0; jj < 4; ++jj)
                    acc[i][jj] = ffma2(av, b[jj], acc[i][jj]);
            }
        }
        __syncthreads();
    }

    // epilogue
    #pragma unroll
    for (int i = 0; i < 8; ++i) {
        int r = rowBase + (ty << 3) + i;
        #pragma unroll
        for (int jj = 0; jj < 4; ++jj) {
            int c = colBase + (tx << 1) + (jj << 5);
            float2 v = acc[i][jj];
            if (bias) { v.x += bias[c]; v.y += bias[c + 1]; }
            float* yp = &Y[(size_t)r*J + c];
            if (ACCUM) {
                float2 old = *reinterpret_cast<float2*>(yp);
                v.x += old.x; v.y += old.y;
            }
            *reinterpret_cast<float2*>(yp) = v;
        }
    }
}

// ---------------------------------------------------------------------------
// Fused 3-layer MLP: state(8192x2) -> relu(W1)->128 -> relu(W2)->64 -> W3->128
// 32 rows per block, grid = 256 blocks, 256 threads.
// ---------------------------------------------------------------------------
__global__ __launch_bounds__(256)
void mlp_kernel(const float* __restrict__ W1, const float* __restrict__ B1,
                const float* __restrict__ W2, const float* __restrict__ B2,
                const float* __restrict__ W3, const float* __restrict__ B3)
{
    __shared__ float s0[32][2];
    __shared__ float h1[32][128];
    __shared__ float h2[32][64];

    const int tid = threadIdx.x;
    const int rb = blockIdx.x << 5;

    for (int s = tid; s < 64; s += 256)
        s0[s >> 1][s & 1] = g_state[rb*2 + s];
    __syncthreads();

    // phase 1: 2 -> 128, relu
    for (int idx = tid; idx < 4096; idx += 256) {
        int r = idx >> 7, j = idx & 127;
        float v = s0[r][0]*W1[2*j] + s0[r][1]*W1[2*j + 1] + B1[j];
        h1[r][j] = fmaxf(v, 0.0f);
    }
    __syncthreads();

    // phase 2: 128 -> 64, relu
    for (int idx = tid; idx < 2048; idx += 256) {
        int r = idx >> 6, j = idx & 63;
        float acc = B2[j];
        const float4* wr = reinterpret_cast<const float4*>(&W2[j*128]);
        const float4* hr = reinterpret_cast<const float4*>(&h1[r][0]);
        #pragma unroll 8
        for (int kq = 0; kq < 32; ++kq) {
            float4 wv = __ldg(&wr[kq]);
            float4 hv = hr[kq];
            acc += wv.x*hv.x + wv.y*hv.y + wv.z*hv.z + wv.w*hv.w;
        }
        h2[r][j] = fmaxf(acc, 0.0f);
    }
    __syncthreads();

    // phase 3: 64 -> 128
    for (int idx = tid; idx < 4096; idx += 256) {
        int r = idx >> 7, j = idx & 127;
        float acc = B3[j];
        const float4* wr = reinterpret_cast<const float4*>(&W3[j*64]);
        const float4* hr = reinterpret_cast<const float4*>(&h2[r][0]);
        #pragma unroll
        for (int kq = 0; kq < 16; ++kq) {
            float4 wv = __ldg(&wr[kq]);
            float4 hv = hr[kq];
            acc += wv.x*hv.x + wv.y*hv.y + wv.z*hv.z + wv.w*hv.w;
        }
        g_e0[(size_t)(rb + r)*NH + j] = acc;
    }
}

// ---------------------------------------------------------------------------
// Cross-attention: one block per (batch, head). 256 threads = 8 warps.
// K/V tiles staged in smem [m][18]; 2 queries per inner group; FFMA2 in both
// score and PV phases; warp-butterfly reduction.
// ---------------------------------------------------------------------------
#define KS_LD 18
#define ATT_SMEM_BYTES ((2*NM*KS_LD + NM)*4)

__global__ __launch_bounds__(256)
void attn_kernel()
{
    extern __shared__ float sm[];
    float* ks    = sm;                    // [512][18]
    float* vs    = sm + NM*KS_LD;         // [512][18]
    float* maskS = vs + NM*KS_LD;         // [512]

    const int tid  = threadIdx.x;
    const int b    = blockIdx.x >> 3;
    const int head = blockIdx.x & 7;
    const size_t kvbase = (size_t)b*NM*NH + head*HD;

    for (int s = tid; s < NM*4; s += 256) {
        int m = s >> 2, dq = (s & 3) << 2;
        float4 kv = *reinterpret_cast<const float4*>(&g_kh[kvbase + (size_t)m*NH + dq]);
        float4 vv = *reinterpret_cast<const float4*>(&g_vh[kvbase + (size_t)m*NH + dq]);
        ks[m*KS_LD + dq + 0] = kv.x; ks[m*KS_LD + dq + 1] = kv.y;
        ks[m*KS_LD + dq + 2] = kv.z; ks[m*KS_LD + dq + 3] = kv.w;
        vs[m*KS_LD + dq + 0] = vv.x; vs[m*KS_LD + dq + 1] = vv.y;
        vs[m*KS_LD + dq + 2] = vv.z; vs[m*KS_LD + dq + 3] = vv.w;
    }
    for (int m = tid; m < NM; m += 256)
        maskS[m] = g_maskadd[b*NM + m];
    __syncthreads();

    const int w = tid >> 5, lane = tid & 31;

    for (int g = 0; g < 4; ++g) {
        const int a0 = (w << 3) + (g << 1);
        const int r0 = b*NA + a0;

        float2 q0[8], q1[8];
        #pragma unroll
        for (int dq = 0; dq < 8; ++dq) {
            q0[dq] = *reinterpret_cast<const float2*>(&g_q[(size_t)r0*NH + head*HD + 2*dq]);
            q1[dq] = *reinterpret_cast<const float2*>(&g_q[(size_t)(r0 + 1)*NH + head*HD + 2*dq]);
        }

        // scores: each lane owns m = lane + 32k, k = 0..15
        float s0[16], s1[16];
        #pragma unroll
        for (int k = 0; k < 16; ++k) {
            int m = lane + (k << 5);
            const float* kr = &ks[m*KS_LD];
            float2 a0v = make_float2(0.0f, 0.0f);
            float2 a1v = make_float2(0.0f, 0.0f);
            #pragma unroll
            for (int dq = 0; dq < 8; ++dq) {
                float2 kvv = *reinterpret_cast<const float2*>(&kr[2*dq]);
                a0v = ffma2(q0[dq], kvv, a0v);
                a1v = ffma2(q1[dq], kvv, a1v);
            }
            float msk = maskS[m];
            s0[k] = (a0v.x + a0v.y)*0.25f + msk;
            s1[k] = (a1v.x + a1v.y)*0.25f + msk;
        }

        // softmax
        float m0 = -1e30f, m1 = -1e30f;
        #pragma unroll
        for (int k = 0; k < 16; ++k) { m0 = fmaxf(m0, s0[k]); m1 = fmaxf(m1, s1[k]); }
        #pragma unroll
        for (int off = 16; off > 0; off >>= 1) {
            m0 = fmaxf(m0, __shfl_xor_sync(0xffffffffu, m0, off));
            m1 = fmaxf(m1, __shfl_xor_sync(0xffffffffu, m1, off));
        }
        float sum0 = 0.0f, sum1 = 0.0f;
        #pragma unroll
        for (int k = 0; k < 16; ++k) {
            s0[k] = __expf(s0[k] - m0); sum0 += s0[k];
            s1[k] = __expf(s1[k] - m1); sum1 += s1[k];
        }
        #pragma unroll
        for (int off = 16; off > 0; off >>= 1) {
            sum0 += __shfl_xor_sync(0xffffffffu, sum0, off);
            sum1 += __shfl_xor_sync(0xffffffffu, sum1, off);
        }

        // PV
        float2 o0[8], o1[8];
        #pragma unroll
        for (int dq = 0; dq < 8; ++dq) {
            o0[dq] = make_float2(0.0f, 0.0f);
            o1[dq] = make_float2(0.0f, 0.0f);
        }
        #pragma unroll
        for (int k = 0; k < 16; ++k) {
            int m = lane + (k << 5);
            const float* vr = &vs[m*KS_LD];
            float2 p0 = make_float2(s0[k], s0[k]);
            float2 p1 = make_float2(s1[k], s1[k]);
            #pragma unroll
            for (int dq = 0; dq < 8; ++dq) {
                float2 vvv = *reinterpret_cast<const float2*>(&vr[2*dq]);
                o0[dq] = ffma2(p0, vvv, o0[dq]);
                o1[dq] = ffma2(p1, vvv, o1[dq]);
            }
        }

        // cross-lane reduction
        #pragma unroll
        for (int dq = 0; dq < 8; ++dq) {
            #pragma unroll
            for (int off = 16; off > 0; off >>= 1) {
                o0[dq] = add2(o0[dq], shfl_xor_f2(o0[dq], off));
                o1[dq] = add2(o1[dq], shfl_xor_f2(o1[dq], off));
            }
        }

        if (lane == 0) {
            float inv0 = 1.0f / sum0, inv1 = 1.0f / sum1;
            float* out0 = &g_attn[(size_t)r0*NH + head*HD];
            float* out1 = &g_attn[(size_t)(r0 + 1)*NH + head*HD];
            #pragma unroll
            for (int dq = 0; dq < 8; ++dq) {
                out0[2*dq + 0] = o0[dq].x * inv0;
                out0[2*dq + 1] = o0[dq].y * inv0;
                out1[2*dq + 0] = o1[dq].x * inv1;
                out1[2*dq + 1] = o1[dq].y * inv1;
            }
        }
    }
}

// ---------------------------------------------------------------------------
// LSTM pointwise: gates(8192x512), update h, c with availability mask.
// ---------------------------------------------------------------------------
__global__ __launch_bounds__(256)
void lstm_kernel()
{
    int gid = blockIdx.x*256 + threadIdx.x;   // gid = row*128 + u
    int row = gid >> 7;
    int u   = gid & 127;
    const float* gr = &g_gates[(size_t)row*512 + u];
    float ig = gr[0], fg = gr[128], gg = gr[256], og = gr[384];
    float c_old = g_c[gid];
    float cn = sigm(fg)*c_old + sigm(ig)*tanhf(gg);
    float hn = sigm(og)*tanhf(cn);
    if (g_curav[row]) {
        g_h[gid] = hn;
        g_c[gid] = cn;
    }
}

// ---------------------------------------------------------------------------
// Residual state update + output write:  state += h @ lin_w^T + lin_b
// 8 warps/block, one row per warp. grid = 1024.
// ---------------------------------------------------------------------------
__global__ __launch_bounds__(256)
void outlin_kernel(const float* __restrict__ lin_w, const float* __restrict__ lin_b,
                   float* __restrict__ out, int t, int T)
{
    const int w = threadIdx.x >> 5, lane = threadIdx.x & 31;
    const int row = blockIdx.x*8 + w;
    float4 hv = *reinterpret_cast<const float4*>(&g_h[(size_t)row*NH + lane*4]);
    float4 w0 = *reinterpret_cast<const float4*>(&lin_w[lane*4]);
    float4 w1 = *reinterpret_cast<const float4*>(&lin_w[128 + lane*4]);
    float2 d;
    d.x = hv.x*w0.x + hv.y*w0.y + hv.z*w0.z + hv.w*w0.w;
    d.y = hv.x*w1.x + hv.y*w1.y + hv.z*w1.z + hv.w*w1.w;
    #pragma unroll
    for (int off = 16; off > 0; off >>= 1)
        d = add2(d, shfl_xor_f2(d, off));
    if (lane == 0) {
        float s0v = g_state[row*2 + 0] + d.x + lin_b[0];
        float s1v = g_state[row*2 + 1] + d.y + lin_b[1];
        g_state[row*2 + 0] = s0v;
        g_state[row*2 + 1] = s1v;
        out[((size_t)row*T + t)*2 + 0] = s0v;
        out[((size_t)row*T + t)*2 + 1] = s1v;
    }
}

// ---------------------------------------------------------------------------
// Per-launch init: state/h/c from inputs, combined LSTM bias, clear detector.
// ---------------------------------------------------------------------------
__global__ void init_kernel(const float* __restrict__ feat,
                            const float* __restrict__ hidden,
                            const float* __restrict__ context,
                            const float* __restrict__ b_ih,
                            const float* __restrict__ b_hh)
{
    int i = blockIdx.x*blockDim.x + threadIdx.x;
    if (i < NROWS*NH) { g_h[i] = hidden[i]; g_c[i] = context[i]; }
    if (i < NROWS*2)  g_state[i] = feat[i];
    if (i < 4*NH)     g_bcomb[i] = b_ih[i] + b_hh[i];
    if (i < 4)        g_viol[i] = 0;
}

// ---------------------------------------------------------------------------
// Host orchestration (graph-capturable: kernel launches only)
// ---------------------------------------------------------------------------
extern "C" void kernel_launch(void* const* d_in, const int* in_sizes, int n_in,
                              void* d_out, int out_size)
{
    // First 6 inputs are positionally stable.
    const float* feat      = (const float*)d_in[0];
    const void*  cur_avail = d_in[1];
    const float* hidden    = (const float*)d_in[2];
    const float* context   = (const float*)d_in[3];
    const float* map_emb   = (const float*)d_in[4];
    const void*  map_avail = d_in[5];

    // The 20 weight/bias tensors are the LAST 20 inputs — index from the end
    // so it doesn't matter whether the n_timesteps scalar is materialized.
    const int wb = n_in - 20;
    const float* enc_w1 = (const float*)d_in[wb + 0];
    const float* enc_b1 = (const float*)d_in[wb + 1];
    const float* enc_w2 = (const float*)d_in[wb + 2];
    const float* enc_b2 = (const float*)d_in[wb + 3];
    const float* enc_w3 = (const float*)d_in[wb + 4];
    const float* enc_b3 = (const float*)d_in[wb + 5];
    const float* wq     = (const float*)d_in[wb + 6];
    const float* bq     = (const float*)d_in[wb + 7];
    const float* wk     = (const float*)d_in[wb + 8];
    const float* bk     = (const float*)d_in[wb + 9];
    const float* wv     = (const float*)d_in[wb + 10];
    const float* bv     = (const float*)d_in[wb + 11];
    const float* wo     = (const float*)d_in[wb + 12];
    const float* bo     = (const float*)d_in[wb + 13];
    const float* w_ih   = (const float*)d_in[wb + 14];
    const float* w_hh   = (const float*)d_in[wb + 15];
    const float* b_ih   = (const float*)d_in[wb + 16];
    const float* b_hh   = (const float*)d_in[wb + 17];
    const float* lin_w  = (const float*)d_in[wb + 18];
    const float* lin_b  = (const float*)d_in[wb + 19];

    float* out = (float*)d_out;
    const int T = out_size / (NROWS*2);

    float *p_kh, *p_vh, *p_e0, *p_q, *p_attn, *p_x, *p_h, *p_gates, *p_bc;
    cudaGetSymbolAddress((void**)&p_kh,    g_kh);
    cudaGetSymbolAddress((void**)&p_vh,    g_vh);
    cudaGetSymbolAddress((void**)&p_e0,    g_e0);
    cudaGetSymbolAddress((void**)&p_q,     g_q);
    cudaGetSymbolAddress((void**)&p_attn,  g_attn);
    cudaGetSymbolAddress((void**)&p_x,     g_x);
    cudaGetSymbolAddress((void**)&p_h,     g_h);
    cudaGetSymbolAddress((void**)&p_gates, g_gates);
    cudaGetSymbolAddress((void**)&p_bc,    g_bcomb);

    cudaFuncSetAttribute(attn_kernel,
                         cudaFuncAttributeMaxDynamicSharedMemorySize,
                         ATT_SMEM_BYTES);

    // init + bool-format detection + mask build
    init_kernel<<<(NROWS*NH + 511)/512, 512>>>(feat, hidden, context, b_ih, b_hh);
    detect_kernel<<<((NB*NM/4) + 255)/256, 256>>>((const unsigned int*)map_avail, NB*NM/4, 0);
    detect_kernel<<<((NROWS/4) + 255)/256, 256>>>((const unsigned int*)cur_avail, NROWS/4, 2);
    build_mask_kernel<<<(NB*NM + 255)/256, 256>>>(map_avail, cur_avail);

    // loop-invariant K/V head projections
    gemm_tn<false><<<dim3(KVROWS/64, 1), 128>>>(map_emb, wk, bk, p_kh, NH, NH);
    gemm_tn<false><<<dim3(KVROWS/64, 1), 128>>>(map_emb, wv, bv, p_vh, NH, NH);

    for (int t = 0; t < T; ++t) {
        // 1. MLP encoder
        mlp_kernel<<<NROWS/32, 256>>>(enc_w1, enc_b1, enc_w2, enc_b2, enc_w3, enc_b3);
        // 2. Q projection
        gemm_tn<false><<<dim3(NROWS/64, 1), 128>>>(p_e0, wq, bq, p_q, NH, NH);
        // 3. cross-attention
        attn_kernel<<<NB*NHEAD, 256, ATT_SMEM_BYTES>>>();
        // 4. output projection
        gemm_tn<false><<<dim3(NROWS/64, 1), 128>>>(p_attn, wo, bo, p_x, NH, NH);
        // 5. LSTM gates: x @ w_ih^T + (b_ih+b_hh), then += h @ w_hh^T
        gemm_tn<false><<<dim3(NROWS/64, 4), 128>>>(p_x, w_ih, p_bc,   p_gates, NH, 4*NH);
        gemm_tn<true ><<<dim3(NROWS/64, 4), 128>>>(p_h, w_hh, nullptr, p_gates, NH, 4*NH);
        // 6. LSTM pointwise update
        lstm_kernel<<<NROWS*NH/256, 256>>>();
        // 7. residual state update + write output slice t
        outlin_kernel<<<NROWS/8, 256>>>(lin_w, lin_b, out, t, T);
    }
}

// round 9
// speedup vs baseline: 1.7682x; 1.7682x over previous
#include <cuda_runtime.h>
#include <cstdint>

// ---------------------------------------------------------------------------
// Problem constants
// ---------------------------------------------------------------------------
#define NB 128          // batch
#define NA 64           // agents
#define NM 512          // map tokens
#define NH 128          // hidden
#define NHEAD 8
#define HD 16           // head dim
#define NROWS (NB*NA)   // 8192
#define KVROWS (NB*NM)  // 65536

// ---------------------------------------------------------------------------
// Scratch (device globals — allocation-free)
// ---------------------------------------------------------------------------
__device__ float g_kh[KVROWS*NH];      // 32 MB  precomputed K heads
__device__ float g_vh[KVROWS*NH];      // 32 MB  precomputed V heads
__device__ float g_state[NROWS*2];
__device__ float g_h[NROWS*NH];
__device__ float g_c[NROWS*NH];
__device__ float g_q[NROWS*NH];        // Q (from fused MLP)
__device__ float g_attn[NROWS*NH];     // attention output
__device__ float g_gates[NROWS*4*NH];  // 16 MB
__device__ float g_maskadd[NB*NM];     // additive attention mask (0 / -1e30)
__device__ int   g_curav[NROWS];       // current availability (0/1)
__device__ int   g_viol[4];            // dtype-detector violation flags
// precomputed folded weights
__device__ float g_Wgate[512*256];     // [w_ih@wo ; w_hh] row-major K=256
__device__ float g_biasg[512];         // b_ih + b_hh + w_ih@bo
__device__ float g_Wq3[128*64];        // wq @ enc_w3
__device__ float g_bq3[128];           // wq @ enc_b3 + bq

// ---------------------------------------------------------------------------
// Packed fp32x2 FMA (Blackwell FFMA2) + helpers
// ---------------------------------------------------------------------------
__device__ __forceinline__ float2 ffma2(float2 a, float2 b, float2 c) {
    unsigned long long ua = *reinterpret_cast<unsigned long long*>(&a);
    unsigned long long ub = *reinterpret_cast<unsigned long long*>(&b);
    unsigned long long uc = *reinterpret_cast<unsigned long long*>(&c);
    unsigned long long ud;
    asm("fma.rn.f32x2 %0, %1, %2, %3;" : "=l"(ud) : "l"(ua), "l"(ub), "l"(uc));
    return *reinterpret_cast<float2*>(&ud);
}
__device__ __forceinline__ float2 shfl_xor_f2(float2 v, int m) {
    unsigned long long u = *reinterpret_cast<unsigned long long*>(&v);
    u = __shfl_xor_sync(0xffffffffu, u, m);
    return *reinterpret_cast<float2*>(&u);
}
__device__ __forceinline__ float2 add2(float2 a, float2 b) {
    return make_float2(a.x + b.x, a.y + b.y);
}
__device__ __forceinline__ float sigm(float x) {
    return 1.0f / (1.0f + __expf(-x));
}

// ---------------------------------------------------------------------------
// Bool-dtype detector (see round 6 notes): classifies int32 / float32 / byte
// bool encodings by scanning the first N/4 words.
// ---------------------------------------------------------------------------
__global__ void detect_kernel(const unsigned int* __restrict__ p, int nwords, int slot)
{
    int i = blockIdx.x*blockDim.x + threadIdx.x;
    if (i >= nwords) return;
    unsigned int w = p[i];
    if (w > 1u)                      atomicOr(&g_viol[slot + 0], 1);
    if (w != 0u && w != 0x3F800000u) atomicOr(&g_viol[slot + 1], 1);
}

__device__ __forceinline__ bool read_bool(const void* p, int idx, int viol32, int violf32)
{
    if (viol32 == 0)  return ((const int*)p)[idx] != 0;
    if (violf32 == 0) return ((const float*)p)[idx] != 0.0f;
    return ((const unsigned char*)p)[idx] != 0;
}

__global__ void build_mask_kernel(const void* __restrict__ map_avail,
                                  const void* __restrict__ cur_avail)
{
    int i = blockIdx.x*blockDim.x + threadIdx.x;
    int v32m = g_viol[0], vf32m = g_viol[1];
    int v32c = g_viol[2], vf32c = g_viol[3];
    if (i < NB*NM)
        g_maskadd[i] = read_bool(map_avail, i, v32m, vf32m) ? 0.0f : -1e30f;
    if (i < NROWS)
        g_curav[i] = read_bool(cur_avail, i, v32c, vf32c) ? 1 : 0;
}

// ---------------------------------------------------------------------------
// Weight folding (one-time):
//   W_gate[j][k<128]  = sum_d w_ih[j][d]*wo[d][k]   (O-proj folded into w_ih)
//   W_gate[j][k>=128] = w_hh[j][k-128]
//   bias_g[j] = b_ih[j]+b_hh[j]+sum_d w_ih[j][d]*bo[d]
// ---------------------------------------------------------------------------
__global__ void precomp_gate(const float* __restrict__ w_ih, const float* __restrict__ w_hh,
                             const float* __restrict__ wo,   const float* __restrict__ b_ih,
                             const float* __restrict__ b_hh, const float* __restrict__ bo)
{
    int idx = blockIdx.x*256 + threadIdx.x;      // 512*256
    int j = idx >> 8, k = idx & 255;
    if (k < 128) {
        float acc = 0.0f;
        #pragma unroll 4
        for (int d = 0; d < 128; ++d) acc += w_ih[j*128 + d] * wo[d*128 + k];
        g_Wgate[j*256 + k] = acc;
    } else {
        g_Wgate[j*256 + k] = w_hh[j*128 + (k - 128)];
    }
    if (idx < 512) {
        float acc = b_ih[idx] + b_hh[idx];
        #pragma unroll 4
        for (int d = 0; d < 128; ++d) acc += w_ih[idx*128 + d] * bo[d];
        g_biasg[idx] = acc;
    }
}

//   Wq3[j][k] = sum_d wq[j][d]*enc_w3[d][k];  bq3[j] = wq@enc_b3 + bq
__global__ void precomp_q(const float* __restrict__ wq, const float* __restrict__ enc_w3,
                          const float* __restrict__ bq, const float* __restrict__ enc_b3)
{
    int idx = blockIdx.x*256 + threadIdx.x;      // 128*64 = 8192
    int j = idx >> 6, k = idx & 63;
    float acc = 0.0f;
    #pragma unroll 4
    for (int d = 0; d < 128; ++d) acc += wq[j*128 + d] * enc_w3[d*64 + k];
    g_Wq3[j*64 + k] = acc;
    if (idx < 128) {
        float a = bq[idx];
        #pragma unroll 4
        for (int d = 0; d < 128; ++d) a += wq[idx*128 + d] * enc_b3[d];
        g_bq3[idx] = a;
    }
}

// ---------------------------------------------------------------------------
// GEMM: Y[M,J] = [X0|X1][M,K] @ W[J,K]^T + bias
// Virtual K-concatenation: cols k<K0 read X0 (stride ld0), else X1 (stride ld1).
// BM=128, BN=128, BK=32, 256 threads. All smem reads are LDS.128; per k-iter
// 4 LDS.128 + 32 FFMA2 (86% fma issue fraction). grid=(M/128, J/128).
// ---------------------------------------------------------------------------
#define XS_LD 132
__global__ __launch_bounds__(256)
void gemm128(const float* __restrict__ X0, int ld0, int K0,
             const float* __restrict__ X1, int ld1,
             const float* __restrict__ W,  const float* __restrict__ bias,
             float* __restrict__ Y, int ldY, int K)
{
    __shared__ float Xs[32][XS_LD];   // k-major
    __shared__ float Ws[32][XS_LD];   // k-major

    const int tid = threadIdx.x;
    const int tx = tid & 15;          // col group base cx = tx*4 (and +64)
    const int ty = tid >> 4;          // rows ty*8 .. ty*8+7
    const int rowBase = blockIdx.x << 7;
    const int colBase = blockIdx.y << 7;
    const int cx = tx << 2;

    float2 acc[8][4];
    #pragma unroll
    for (int i = 0; i < 8; ++i)
        #pragma unroll
        for (int jj = 0; jj < 4; ++jj)
            acc[i][jj] = make_float2(0.0f, 0.0f);

    for (int k0 = 0; k0 < K; k0 += 32) {
        const float* Xp; int ld;
        if (k0 < K0) { Xp = X0 + k0;        ld = ld0; }
        else         { Xp = X1 + (k0 - K0); ld = ld1; }

        // X tile: 128 rows x 32 k  (1024 float4, 4/thread), store k-major
        #pragma unroll
        for (int i = 0; i < 4; ++i) {
            int s = tid + (i << 8);
            int r = s >> 3, kq = (s & 7) << 2;
            float4 v = *reinterpret_cast<const float4*>(&Xp[(size_t)(rowBase + r)*ld + kq]);
            Xs[kq + 0][r] = v.x; Xs[kq + 1][r] = v.y;
            Xs[kq + 2][r] = v.z; Xs[kq + 3][r] = v.w;
        }
        // W tile: 128 j x 32 k, store k-major
        #pragma unroll
        for (int i = 0; i < 4; ++i) {
            int s = tid + (i << 8);
            int j = s >> 3, kq = (s & 7) << 2;
            float4 v = *reinterpret_cast<const float4*>(&W[(size_t)(colBase + j)*K + k0 + kq]);
            Ws[kq + 0][j] = v.x; Ws[kq + 1][j] = v.y;
            Ws[kq + 2][j] = v.z; Ws[kq + 3][j] = v.w;
        }
        __syncthreads();

        #pragma unroll 8
        for (int k = 0; k < 32; ++k) {
            float4 a0 = *reinterpret_cast<const float4*>(&Xs[k][ty << 3]);
            float4 a1 = *reinterpret_cast<const float4*>(&Xs[k][(ty << 3) + 4]);
            float4 b0 = *reinterpret_cast<const float4*>(&Ws[k][cx]);
            float4 b1 = *reinterpret_cast<const float4*>(&Ws[k][cx + 64]);
            float2 b0l = make_float2(b0.x, b0.y), b0h = make_float2(b0.z, b0.w);
            float2 b1l = make_float2(b1.x, b1.y), b1h = make_float2(b1.z, b1.w);
            float ar[8] = {a0.x, a0.y, a0.z, a0.w, a1.x, a1.y, a1.z, a1.w};
            #pragma unroll
            for (int i = 0; i < 8; ++i) {
                float2 av = make_float2(ar[i], ar[i]);
                acc[i][0] = ffma2(av, b0l, acc[i][0]);
                acc[i][1] = ffma2(av, b0h, acc[i][1]);
                acc[i][2] = ffma2(av, b1l, acc[i][2]);
                acc[i][3] = ffma2(av, b1h, acc[i][3]);
            }
        }
        __syncthreads();
    }

    float4 bi0 = *reinterpret_cast<const float4*>(&bias[colBase + cx]);
    float4 bi1 = *reinterpret_cast<const float4*>(&bias[colBase + cx + 64]);
    #pragma unroll
    for (int i = 0; i < 8; ++i) {
        int r = rowBase + (ty << 3) + i;
        float4 v0 = make_float4(acc[i][0].x + bi0.x, acc[i][0].y + bi0.y,
                                acc[i][1].x + bi0.z, acc[i][1].y + bi0.w);
        float4 v1 = make_float4(acc[i][2].x + bi1.x, acc[i][2].y + bi1.y,
                                acc[i][3].x + bi1.z, acc[i][3].y + bi1.w);
        *reinterpret_cast<float4*>(&Y[(size_t)r*ldY + colBase + cx])      = v0;
        *reinterpret_cast<float4*>(&Y[(size_t)r*ldY + colBase + cx + 64]) = v1;
    }
}

// ---------------------------------------------------------------------------
// Fused MLP + Q: state(2) -> relu(W1)->128 -> relu(W2)->64 -> q = h2@Wq3^T+bq3
// 32 rows/block, 256 threads, grid 256.
// ---------------------------------------------------------------------------
__global__ __launch_bounds__(256)
void mlpq_kernel(const float* __restrict__ W1, const float* __restrict__ B1,
                 const float* __restrict__ W2, const float* __restrict__ B2)
{
    __shared__ float s0[32][2];
    __shared__ float h1[32][128];
    __shared__ float h2[32][68];

    const int tid = threadIdx.x;
    const int rb = blockIdx.x << 5;

    for (int s = tid; s < 64; s += 256)
        s0[s >> 1][s & 1] = g_state[rb*2 + s];
    __syncthreads();

    for (int idx = tid; idx < 4096; idx += 256) {
        int r = idx >> 7, j = idx & 127;
        float v = s0[r][0]*W1[2*j] + s0[r][1]*W1[2*j + 1] + B1[j];
        h1[r][j] = fmaxf(v, 0.0f);
    }
    __syncthreads();

    for (int idx = tid; idx < 2048; idx += 256) {
        int r = idx >> 6, j = idx & 63;
        float acc = B2[j];
        const float4* wr = reinterpret_cast<const float4*>(&W2[j*128]);
        const float4* hr = reinterpret_cast<const float4*>(&h1[r][0]);
        #pragma unroll 8
        for (int kq = 0; kq < 32; ++kq) {
            float4 wv = __ldg(&wr[kq]);
            float4 hv = hr[kq];
            acc += wv.x*hv.x + wv.y*hv.y + wv.z*hv.z + wv.w*hv.w;
        }
        h2[r][j] = fmaxf(acc, 0.0f);
    }
    __syncthreads();

    for (int idx = tid; idx < 4096; idx += 256) {
        int r = idx >> 7, j = idx & 127;
        float acc = g_bq3[j];
        const float4* wr = reinterpret_cast<const float4*>(&g_Wq3[j*64]);
        const float4* hr = reinterpret_cast<const float4*>(&h2[r][0]);
        #pragma unroll
        for (int kq = 0; kq < 16; ++kq) {
            float4 wv = __ldg(&wr[kq]);
            float4 hv = hr[kq];
            acc += wv.x*hv.x + wv.y*hv.y + wv.z*hv.z + wv.w*hv.w;
        }
        g_q[(size_t)(rb + r)*NH + j] = acc;
    }
}

// ---------------------------------------------------------------------------
// Cross-attention (unchanged from passing version): block per (batch, head).
// ---------------------------------------------------------------------------
#define KS_LD 18
#define ATT_SMEM_BYTES ((2*NM*KS_LD + NM)*4)

__global__ __launch_bounds__(256)
void attn_kernel()
{
    extern __shared__ float sm[];
    float* ks    = sm;
    float* vs    = sm + NM*KS_LD;
    float* maskS = vs + NM*KS_LD;

    const int tid  = threadIdx.x;
    const int b    = blockIdx.x >> 3;
    const int head = blockIdx.x & 7;
    const size_t kvbase = (size_t)b*NM*NH + head*HD;

    for (int s = tid; s < NM*4; s += 256) {
        int m = s >> 2, dq = (s & 3) << 2;
        float4 kv = *reinterpret_cast<const float4*>(&g_kh[kvbase + (size_t)m*NH + dq]);
        float4 vv = *reinterpret_cast<const float4*>(&g_vh[kvbase + (size_t)m*NH + dq]);
        ks[m*KS_LD + dq + 0] = kv.x; ks[m*KS_LD + dq + 1] = kv.y;
        ks[m*KS_LD + dq + 2] = kv.z; ks[m*KS_LD + dq + 3] = kv.w;
        vs[m*KS_LD + dq + 0] = vv.x; vs[m*KS_LD + dq + 1] = vv.y;
        vs[m*KS_LD + dq + 2] = vv.z; vs[m*KS_LD + dq + 3] = vv.w;
    }
    for (int m = tid; m < NM; m += 256)
        maskS[m] = g_maskadd[b*NM + m];
    __syncthreads();

    const int w = tid >> 5, lane = tid & 31;

    for (int g = 0; g < 4; ++g) {
        const int a0 = (w << 3) + (g << 1);
        const int r0 = b*NA + a0;

        float2 q0[8], q1[8];
        #pragma unroll
        for (int dq = 0; dq < 8; ++dq) {
            q0[dq] = *reinterpret_cast<const float2*>(&g_q[(size_t)r0*NH + head*HD + 2*dq]);
            q1[dq] = *reinterpret_cast<const float2*>(&g_q[(size_t)(r0 + 1)*NH + head*HD + 2*dq]);
        }

        float s0[16], s1[16];
        #pragma unroll
        for (int k = 0; k < 16; ++k) {
            int m = lane + (k << 5);
            const float* kr = &ks[m*KS_LD];
            float2 a0v = make_float2(0.0f, 0.0f);
            float2 a1v = make_float2(0.0f, 0.0f);
            #pragma unroll
            for (int dq = 0; dq < 8; ++dq) {
                float2 kvv = *reinterpret_cast<const float2*>(&kr[2*dq]);
                a0v = ffma2(q0[dq], kvv, a0v);
                a1v = ffma2(q1[dq], kvv, a1v);
            }
            float msk = maskS[m];
            s0[k] = (a0v.x + a0v.y)*0.25f + msk;
            s1[k] = (a1v.x + a1v.y)*0.25f + msk;
        }

        float m0 = -1e30f, m1 = -1e30f;
        #pragma unroll
        for (int k = 0; k < 16; ++k) { m0 = fmaxf(m0, s0[k]); m1 = fmaxf(m1, s1[k]); }
        #pragma unroll
        for (int off = 16; off > 0; off >>= 1) {
            m0 = fmaxf(m0, __shfl_xor_sync(0xffffffffu, m0, off));
            m1 = fmaxf(m1, __shfl_xor_sync(0xffffffffu, m1, off));
        }
        float sum0 = 0.0f, sum1 = 0.0f;
        #pragma unroll
        for (int k = 0; k < 16; ++k) {
            s0[k] = __expf(s0[k] - m0); sum0 += s0[k];
            s1[k] = __expf(s1[k] - m1); sum1 += s1[k];
        }
        #pragma unroll
        for (int off = 16; off > 0; off >>= 1) {
            sum0 += __shfl_xor_sync(0xffffffffu, sum0, off);
            sum1 += __shfl_xor_sync(0xffffffffu, sum1, off);
        }

        float2 o0[8], o1[8];
        #pragma unroll
        for (int dq = 0; dq < 8; ++dq) {
            o0[dq] = make_float2(0.0f, 0.0f);
            o1[dq] = make_float2(0.0f, 0.0f);
        }
        #pragma unroll
        for (int k = 0; k < 16; ++k) {
            int m = lane + (k << 5);
            const float* vr = &vs[m*KS_LD];
            float2 p0 = make_float2(s0[k], s0[k]);
            float2 p1 = make_float2(s1[k], s1[k]);
            #pragma unroll
            for (int dq = 0; dq < 8; ++dq) {
                float2 vvv = *reinterpret_cast<const float2*>(&vr[2*dq]);
                o0[dq] = ffma2(p0, vvv, o0[dq]);
                o1[dq] = ffma2(p1, vvv, o1[dq]);
            }
        }

        #pragma unroll
        for (int dq = 0; dq < 8; ++dq) {
            #pragma unroll
            for (int off = 16; off > 0; off >>= 1) {
                o0[dq] = add2(o0[dq], shfl_xor_f2(o0[dq], off));
                o1[dq] = add2(o1[dq], shfl_xor_f2(o1[dq], off));
            }
        }

        if (lane == 0) {
            float inv0 = 1.0f / sum0, inv1 = 1.0f / sum1;
            float* out0 = &g_attn[(size_t)r0*NH + head*HD];
            float* out1 = &g_attn[(size_t)(r0 + 1)*NH + head*HD];
            #pragma unroll
            for (int dq = 0; dq < 8; ++dq) {
                out0[2*dq + 0] = o0[dq].x * inv0;
                out0[2*dq + 1] = o0[dq].y * inv0;
                out1[2*dq + 0] = o1[dq].x * inv1;
                out1[2*dq + 1] = o1[dq].y * inv1;
            }
        }
    }
}

// ---------------------------------------------------------------------------
// Fused LSTM pointwise + residual output linear.
// 8 warps/block, 1 row per warp, lane owns 4 hidden units. grid = 1024.
// ---------------------------------------------------------------------------
__global__ __launch_bounds__(256)
void lstmout_kernel(const float* __restrict__ lin_w, const float* __restrict__ lin_b,
                    float* __restrict__ out, int t, int T)
{
    const int w = threadIdx.x >> 5, lane = threadIdx.x & 31;
    const int row = blockIdx.x*8 + w;
    const int u0 = lane << 2;
    const float* gr = &g_gates[(size_t)row*512];

    float4 ig = *reinterpret_cast<const float4*>(&gr[u0]);
    float4 fg = *reinterpret_cast<const float4*>(&gr[u0 + 128]);
    float4 gg = *reinterpret_cast<const float4*>(&gr[u0 + 256]);
    float4 og = *reinterpret_cast<const float4*>(&gr[u0 + 384]);
    float4 cold = *reinterpret_cast<const float4*>(&g_c[(size_t)row*NH + u0]);
    float4 hold = *reinterpret_cast<const float4*>(&g_h[(size_t)row*NH + u0]);

    float4 cn, hn;
    cn.x = sigm(fg.x)*cold.x + sigm(ig.x)*tanhf(gg.x);
    cn.y = sigm(fg.y)*cold.y + sigm(ig.y)*tanhf(gg.y);
    cn.z = sigm(fg.z)*cold.z + sigm(ig.z)*tanhf(gg.z);
    cn.w = sigm(fg.w)*cold.w + sigm(ig.w)*tanhf(gg.w);
    hn.x = sigm(og.x)*tanhf(cn.x);
    hn.y = sigm(og.y)*tanhf(cn.y);
    hn.z = sigm(og.z)*tanhf(cn.z);
    hn.w = sigm(og.w)*tanhf(cn.w);

    int avail = g_curav[row];
    float4 hsel = avail ? hn : hold;
    if (avail) {
        *reinterpret_cast<float4*>(&g_h[(size_t)row*NH + u0]) = hn;
        *reinterpret_cast<float4*>(&g_c[(size_t)row*NH + u0]) = cn;
    }

    float4 w0 = *reinterpret_cast<const float4*>(&lin_w[u0]);
    float4 w1 = *reinterpret_cast<const float4*>(&lin_w[128 + u0]);
    float2 d;
    d.x = hsel.x*w0.x + hsel.y*w0.y + hsel.z*w0.z + hsel.w*w0.w;
    d.y = hsel.x*w1.x + hsel.y*w1.y + hsel.z*w1.z + hsel.w*w1.w;
    #pragma unroll
    for (int off = 16; off > 0; off >>= 1)
        d = add2(d, shfl_xor_f2(d, off));
    if (lane == 0) {
        float s0v = g_state[row*2 + 0] + d.x + lin_b[0];
        float s1v = g_state[row*2 + 1] + d.y + lin_b[1];
        g_state[row*2 + 0] = s0v;
        g_state[row*2 + 1] = s1v;
        out[((size_t)row*T + t)*2 + 0] = s0v;
        out[((size_t)row*T + t)*2 + 1] = s1v;
    }
}

// ---------------------------------------------------------------------------
// Per-launch init
// ---------------------------------------------------------------------------
__global__ void init_kernel(const float* __restrict__ feat,
                            const float* __restrict__ hidden,
                            const float* __restrict__ context)
{
    int i = blockIdx.x*blockDim.x + threadIdx.x;
    if (i < NROWS*NH) { g_h[i] = hidden[i]; g_c[i] = context[i]; }
    if (i < NROWS*2)  g_state[i] = feat[i];
    if (i < 4)        g_viol[i] = 0;
}

// ---------------------------------------------------------------------------
// Host orchestration (graph-capturable: kernel launches only)
// ---------------------------------------------------------------------------
extern "C" void kernel_launch(void* const* d_in, const int* in_sizes, int n_in,
                              void* d_out, int out_size)
{
    const float* feat      = (const float*)d_in[0];
    const void*  cur_avail = d_in[1];
    const float* hidden    = (const float*)d_in[2];
    const float* context   = (const float*)d_in[3];
    const float* map_emb   = (const float*)d_in[4];
    const void*  map_avail = d_in[5];

    const int wb = n_in - 20;  // weights are the LAST 20 inputs
    const float* enc_w1 = (const float*)d_in[wb + 0];
    const float* enc_b1 = (const float*)d_in[wb + 1];
    const float* enc_w2 = (const float*)d_in[wb + 2];
    const float* enc_b2 = (const float*)d_in[wb + 3];
    const float* enc_w3 = (const float*)d_in[wb + 4];
    const float* enc_b3 = (const float*)d_in[wb + 5];
    const float* wq     = (const float*)d_in[wb + 6];
    const float* bq     = (const float*)d_in[wb + 7];
    const float* wk     = (const float*)d_in[wb + 8];
    const float* bk     = (const float*)d_in[wb + 9];
    const float* wv     = (const float*)d_in[wb + 10];
    const float* bv     = (const float*)d_in[wb + 11];
    const float* wo     = (const float*)d_in[wb + 12];
    const float* bo     = (const float*)d_in[wb + 13];
    const float* w_ih   = (const float*)d_in[wb + 14];
    const float* w_hh   = (const float*)d_in[wb + 15];
    const float* b_ih   = (const float*)d_in[wb + 16];
    const float* b_hh   = (const float*)d_in[wb + 17];
    const float* lin_w  = (const float*)d_in[wb + 18];
    const float* lin_b  = (const float*)d_in[wb + 19];

    float* out = (float*)d_out;
    const int T = out_size / (NROWS*2);

    float *p_kh, *p_vh, *p_attn, *p_h, *p_gates, *p_Wg, *p_bg;
    cudaGetSymbolAddress((void**)&p_kh,    g_kh);
    cudaGetSymbolAddress((void**)&p_vh,    g_vh);
    cudaGetSymbolAddress((void**)&p_attn,  g_attn);
    cudaGetSymbolAddress((void**)&p_h,     g_h);
    cudaGetSymbolAddress((void**)&p_gates, g_gates);
    cudaGetSymbolAddress((void**)&p_Wg,    g_Wgate);
    cudaGetSymbolAddress((void**)&p_bg,    g_biasg);

    cudaFuncSetAttribute(attn_kernel,
                         cudaFuncAttributeMaxDynamicSharedMemorySize,
                         ATT_SMEM_BYTES);

    // init + bool-format detection + mask build + weight folding
    init_kernel<<<(NROWS*NH + 511)/512, 512>>>(feat, hidden, context);
    detect_kernel<<<((NB*NM/4) + 255)/256, 256>>>((const unsigned int*)map_avail, NB*NM/4, 0);
    detect_kernel<<<((NROWS/4) + 255)/256, 256>>>((const unsigned int*)cur_avail, NROWS/4, 2);
    build_mask_kernel<<<(NB*NM + 255)/256, 256>>>(map_avail, cur_avail);
    precomp_gate<<<512, 256>>>(w_ih, w_hh, wo, b_ih, b_hh, bo);
    precomp_q<<<32, 256>>>(wq, enc_w3, bq, enc_b3);

    // loop-invariant K/V head projections
    gemm128<<<dim3(KVROWS/128, 1), 256>>>(map_emb, NH, NH, map_emb, NH, wk, bk, p_kh, NH, NH);
    gemm128<<<dim3(KVROWS/128, 1), 256>>>(map_emb, NH, NH, map_emb, NH, wv, bv, p_vh, NH, NH);

    for (int t = 0; t < T; ++t) {
        // 1. fused MLP + Q projection
        mlpq_kernel<<<NROWS/32, 256>>>(enc_w1, enc_b1, enc_w2, enc_b2);
        // 2. cross-attention
        attn_kernel<<<NB*NHEAD, 256, ATT_SMEM_BYTES>>>();
        // 3. fused gates GEMM: [attn | h] (K=256) @ W_gate^T + bias_g
        gemm128<<<dim3(NROWS/128, 4), 256>>>(p_attn, NH, NH, p_h, NH, p_Wg, p_bg,
                                             p_gates, 4*NH, 2*NH);
        // 4. fused LSTM pointwise + residual output linear
        lstmout_kernel<<<NROWS/8, 256>>>(lin_w, lin_b, out, t, T);
    }
}